// round 12
// baseline (speedup 1.0000x reference)
#include <cuda_runtime.h>
#include <cuda_fp16.h>
#include <math.h>
#include <stdint.h>

#define NN 50000
#define NE 640000
#define W 128
#define NBLK 196   // (NN+255)/256

#define QMAX   32704.0f
#define QMAXI  (1.0f / 32704.0f)
#define MAGC   8421376.0f        // 2^23 + 32768

// ---------------- scratch (device globals: no allocation allowed) ----------------
__device__ int   g_is64;
__device__ int   g_deg[NN];
__device__ float g_dis[NN];
__device__ int   g_rowptr[NN + 1];
__device__ int   g_fill[NN];
__device__ int   g_csr_src[NE];
__device__ float g_csr_w[NE];
__device__ int   g_bsum[NBLK];
__device__ int   g_boff[NBLK];

// int16 T buffers with per-row dequant scales
__device__ uint2 g_T1q[(size_t)NN * 32];
__device__ uint2 g_T2q[(size_t)NN * 32];
__device__ uint2 g_T3q[(size_t)NN * 32];
__device__ uint2 g_T4q[(size_t)NN * 32];
__device__ float g_rs1[NN];
__device__ float g_rs2[NN];
__device__ float g_rs3[NN];
__device__ float g_rs4[NN];

__device__ float g_HA[(size_t)NN * W];
__device__ float g_HB[(size_t)NN * W];

__device__ float g_U [(size_t)NN * 8];
__device__ float g_Y1[(size_t)NN * 8];
__device__ float g_Y2[(size_t)NN * 8];
__device__ float g_Y3[(size_t)NN * 8];
__device__ float g_Y4[(size_t)NN * 8];
__device__ float g_WT[5 * W];
__device__ float g_c0;

// ---------------- int16 helpers ----------------
__device__ __forceinline__ void deq4(uint2 u, float& q0, float& q1, float& q2, float& q3) {
    unsigned a = u.x ^ 0x80008000u;
    unsigned b = u.y ^ 0x80008000u;
    q0 = __uint_as_float(__byte_perm(a, 0x4B000000u, 0x7410)) - MAGC;
    q1 = __uint_as_float(__byte_perm(a, 0x4B000000u, 0x7432)) - MAGC;
    q2 = __uint_as_float(__byte_perm(b, 0x4B000000u, 0x7410)) - MAGC;
    q3 = __uint_as_float(__byte_perm(b, 0x4B000000u, 0x7432)) - MAGC;
}

// warp-wide rowmax -> quantize 4 values; lane0 stores dequant scale
__device__ __forceinline__ uint2 quant_row(
    float r0, float r1, float r2, float r3,
    int lane, float* rs_out, int node)
{
    float m = fmaxf(fmaxf(fabsf(r0), fabsf(r1)), fmaxf(fabsf(r2), fabsf(r3)));
#pragma unroll
    for (int off = 16; off > 0; off >>= 1)
        m = fmaxf(m, __shfl_xor_sync(0xffffffffu, m, off));
    float qs = (m > 0.f) ? (QMAX / m) : 0.f;
    if (lane == 0) rs_out[node] = m * QMAXI;
    int v0 = __float2int_rn(r0 * qs);
    int v1 = __float2int_rn(r1 * qs);
    int v2 = __float2int_rn(r2 * qs);
    int v3 = __float2int_rn(r3 * qs);
    uint2 o;
    o.x = ((unsigned)v0 & 0xFFFFu) | ((unsigned)v1 << 16);
    o.y = ((unsigned)v2 & 0xFFFFu) | ((unsigned)v3 << 16);
    return o;
}

// ---------------- dtype detection ----------------
__global__ void detect_kernel(const int* __restrict__ ei) {
    __shared__ int any;
    if (threadIdx.x == 0) any = 0;
    __syncthreads();
    for (int i = threadIdx.x; i < 4096; i += blockDim.x)
        if (ei[2 * i + 1] != 0) any = 1;
    __syncthreads();
    if (threadIdx.x == 0) g_is64 = (any == 0) ? 1 : 0;
}

__device__ __forceinline__ int load_edge(const void* ei, long long idx, int is64) {
    if (is64) return (int)((const long long*)ei)[idx];
    return ((const int*)ei)[idx];
}

// ---------------- CSR build ----------------
__global__ void init_kernel() {
    int i = blockIdx.x * blockDim.x + threadIdx.x;
    if (i < NN) { g_deg[i] = 0; g_fill[i] = 0; }
}

__global__ void deg_kernel(const void* __restrict__ ei) {
    int e = blockIdx.x * blockDim.x + threadIdx.x;
    if (e >= NE) return;
    int is64 = g_is64;
    int d = load_edge(ei, (long long)NE + e, is64);
    atomicAdd(&g_deg[d], 1);
}

__global__ void dsum_kernel() {
    __shared__ int sdata[256];
    int t = threadIdx.x;
    int i = blockIdx.x * 256 + t;
    int d = (i < NN) ? g_deg[i] : 0;
    if (i < NN) g_dis[i] = (d > 0) ? rsqrtf((float)d) : 0.0f;
    sdata[t] = d;
    __syncthreads();
    for (int s = 128; s > 0; s >>= 1) {
        if (t < s) sdata[t] += sdata[t + s];
        __syncthreads();
    }
    if (t == 0) g_bsum[blockIdx.x] = sdata[0];
}

__global__ void bscan_kernel() {
    __shared__ int s[256];
    int t = threadIdx.x;
    int v = (t < NBLK) ? g_bsum[t] : 0;
    s[t] = v;
    __syncthreads();
    for (int off = 1; off < 256; off <<= 1) {
        int u = (t >= off) ? s[t - off] : 0;
        __syncthreads();
        s[t] += u;
        __syncthreads();
    }
    if (t < NBLK) g_boff[t] = (t == 0) ? 0 : s[t - 1];
}

__global__ void rowptr_kernel() {
    __shared__ int s[256];
    int t = threadIdx.x;
    int i = blockIdx.x * 256 + t;
    int d = (i < NN) ? g_deg[i] : 0;
    s[t] = d;
    __syncthreads();
    for (int off = 1; off < 256; off <<= 1) {
        int u = (t >= off) ? s[t - off] : 0;
        __syncthreads();
        s[t] += u;
        __syncthreads();
    }
    if (i < NN) g_rowptr[i] = g_boff[blockIdx.x] + s[t] - d;
    if (i == NN - 1) g_rowptr[NN] = NE;
}

__global__ void fill_kernel(const void* __restrict__ ei) {
    int e = blockIdx.x * blockDim.x + threadIdx.x;
    if (e >= NE) return;
    int is64 = g_is64;
    int s = load_edge(ei, e, is64);
    int d = load_edge(ei, (long long)NE + e, is64);
    int pos = atomicAdd(&g_fill[d], 1);
    int idx = g_rowptr[d] + pos;
    g_csr_src[idx] = s;
    g_csr_w[idx]   = -g_dis[s] * g_dis[d];
}

#define PROP_BLOCKS 1184   // 148 SMs * 8 CTAs

// ---------------- prop A: T1q = quant(L @ H)  (fp32 gather) --------------------
__global__ void __launch_bounds__(256) propA_kernel(
    const float* __restrict__ X, uint2* __restrict__ outq, float* __restrict__ rs_out)
{
    const int lane = threadIdx.x & 31;
    const int warp0 = (blockIdx.x * blockDim.x + threadIdx.x) >> 5;
    const int wstride = (PROP_BLOCKS * 256) >> 5;
    const float4* X4 = (const float4*)X;

    for (int node = warp0; node < NN; node += wstride) {
        int start = g_rowptr[node];
        int end   = g_rowptr[node + 1];
        float4 acc = make_float4(0.f, 0.f, 0.f, 0.f);
        int i = start;
        for (; i + 1 < end; i += 2) {
            int s0 = g_csr_src[i];     float w0 = g_csr_w[i];
            int s1 = g_csr_src[i + 1]; float w1 = g_csr_w[i + 1];
            float4 v0 = X4[(size_t)s0 * 32 + lane];
            float4 v1 = X4[(size_t)s1 * 32 + lane];
            acc.x += w0 * v0.x; acc.y += w0 * v0.y; acc.z += w0 * v0.z; acc.w += w0 * v0.w;
            acc.x += w1 * v1.x; acc.y += w1 * v1.y; acc.z += w1 * v1.z; acc.w += w1 * v1.w;
        }
        if (i < end) {
            int s0 = g_csr_src[i]; float w0 = g_csr_w[i];
            float4 v0 = X4[(size_t)s0 * 32 + lane];
            acc.x += w0 * v0.x; acc.y += w0 * v0.y; acc.z += w0 * v0.z; acc.w += w0 * v0.w;
        }
        outq[(size_t)node * 32 + lane] =
            quant_row(acc.x, acc.y, acc.z, acc.w, lane, rs_out, node);
    }
}

// ---------------- prop B: T2q = quant(2 L T1q - H)  (int16 gather, fp32 prev) --
__global__ void __launch_bounds__(256) propB_kernel(
    const uint2* __restrict__ Xq, const float* __restrict__ rs_x,
    const float* __restrict__ prev,
    uint2* __restrict__ outq, float* __restrict__ rs_out)
{
    const int lane = threadIdx.x & 31;
    const int warp0 = (blockIdx.x * blockDim.x + threadIdx.x) >> 5;
    const int wstride = (PROP_BLOCKS * 256) >> 5;

    for (int node = warp0; node < NN; node += wstride) {
        int start = g_rowptr[node];
        int end   = g_rowptr[node + 1];
        float a0 = 0.f, a1 = 0.f, a2 = 0.f, a3 = 0.f;
        int i = start;
        for (; i + 1 < end; i += 2) {
            int s0 = g_csr_src[i];     float w0 = g_csr_w[i] * rs_x[s0];
            int s1 = g_csr_src[i + 1]; float w1 = g_csr_w[i + 1] * rs_x[s1];
            uint2 u0 = Xq[(size_t)s0 * 32 + lane];
            uint2 u1 = Xq[(size_t)s1 * 32 + lane];
            float q00, q01, q02, q03, q10, q11, q12, q13;
            deq4(u0, q00, q01, q02, q03);
            deq4(u1, q10, q11, q12, q13);
            a0 = fmaf(w0, q00, a0); a1 = fmaf(w0, q01, a1);
            a2 = fmaf(w0, q02, a2); a3 = fmaf(w0, q03, a3);
            a0 = fmaf(w1, q10, a0); a1 = fmaf(w1, q11, a1);
            a2 = fmaf(w1, q12, a2); a3 = fmaf(w1, q13, a3);
        }
        if (i < end) {
            int s0 = g_csr_src[i]; float w0 = g_csr_w[i] * rs_x[s0];
            uint2 u0 = Xq[(size_t)s0 * 32 + lane];
            float q00, q01, q02, q03;
            deq4(u0, q00, q01, q02, q03);
            a0 = fmaf(w0, q00, a0); a1 = fmaf(w0, q01, a1);
            a2 = fmaf(w0, q02, a2); a3 = fmaf(w0, q03, a3);
        }
        float4 p = ((const float4*)prev)[(size_t)node * 32 + lane];
        outq[(size_t)node * 32 + lane] =
            quant_row(2.f * a0 - p.x, 2.f * a1 - p.y,
                      2.f * a2 - p.z, 2.f * a3 - p.w, lane, rs_out, node);
    }
}

// ---------------- prop C/D: outq = quant(2 L Xq - prevq)  (all int16) ----------
__global__ void __launch_bounds__(256) propQQ_kernel(
    const uint2* __restrict__ Xq, const float* __restrict__ rs_x,
    const uint2* __restrict__ prevq, const float* __restrict__ rs_p,
    uint2* __restrict__ outq, float* __restrict__ rs_out)
{
    const int lane = threadIdx.x & 31;
    const int warp0 = (blockIdx.x * blockDim.x + threadIdx.x) >> 5;
    const int wstride = (PROP_BLOCKS * 256) >> 5;

    for (int node = warp0; node < NN; node += wstride) {
        int start = g_rowptr[node];
        int end   = g_rowptr[node + 1];
        float a0 = 0.f, a1 = 0.f, a2 = 0.f, a3 = 0.f;
        int i = start;
        for (; i + 1 < end; i += 2) {
            int s0 = g_csr_src[i];     float w0 = g_csr_w[i] * rs_x[s0];
            int s1 = g_csr_src[i + 1]; float w1 = g_csr_w[i + 1] * rs_x[s1];
            uint2 u0 = Xq[(size_t)s0 * 32 + lane];
            uint2 u1 = Xq[(size_t)s1 * 32 + lane];
            float q00, q01, q02, q03, q10, q11, q12, q13;
            deq4(u0, q00, q01, q02, q03);
            deq4(u1, q10, q11, q12, q13);
            a0 = fmaf(w0, q00, a0); a1 = fmaf(w0, q01, a1);
            a2 = fmaf(w0, q02, a2); a3 = fmaf(w0, q03, a3);
            a0 = fmaf(w1, q10, a0); a1 = fmaf(w1, q11, a1);
            a2 = fmaf(w1, q12, a2); a3 = fmaf(w1, q13, a3);
        }
        if (i < end) {
            int s0 = g_csr_src[i]; float w0 = g_csr_w[i] * rs_x[s0];
            uint2 u0 = Xq[(size_t)s0 * 32 + lane];
            float q00, q01, q02, q03;
            deq4(u0, q00, q01, q02, q03);
            a0 = fmaf(w0, q00, a0); a1 = fmaf(w0, q01, a1);
            a2 = fmaf(w0, q02, a2); a3 = fmaf(w0, q03, a3);
        }
        uint2 pu = prevq[(size_t)node * 32 + lane];
        float pr = rs_p[node];
        float p0, p1, p2, p3;
        deq4(pu, p0, p1, p2, p3);
        outq[(size_t)node * 32 + lane] =
            quant_row(2.f * a0 - p0 * pr, 2.f * a1 - p1 * pr,
                      2.f * a2 - p2 * pr, 2.f * a3 - p3 * pr, lane, rs_out, node);
    }
}

// ---------------- tensor-core fused 5-term GEMM (split-fp16, fp32-grade) --------
// term 0 = H fp32; terms 1-4 int16 with per-row scales
struct Ptr5m {
    const float* f0;
    const uint4* q[4];
    const float* rs[4];
};

#define KPAD 24

__device__ __forceinline__ void mma16816(float c[4], const unsigned a[4], const unsigned b0, const unsigned b1) {
    asm volatile(
        "mma.sync.aligned.m16n8k16.row.col.f32.f16.f16.f32 "
        "{%0,%1,%2,%3}, {%4,%5,%6,%7}, {%8,%9}, {%0,%1,%2,%3};"
        : "+f"(c[0]), "+f"(c[1]), "+f"(c[2]), "+f"(c[3])
        : "r"(a[0]), "r"(a[1]), "r"(a[2]), "r"(a[3]), "r"(b0), "r"(b1));
}

__device__ __forceinline__ void ldm4(unsigned r[4], unsigned addr) {
    asm volatile("ldmatrix.sync.aligned.m8n8.x4.shared.b16 {%0,%1,%2,%3}, [%4];"
        : "=r"(r[0]), "=r"(r[1]), "=r"(r[2]), "=r"(r[3]) : "r"(addr));
}

__global__ void __launch_bounds__(256) gemm5_mma_kernel(
    Ptr5m T, const float* __restrict__ Wc, const float* __restrict__ bias,
    float* __restrict__ out, int relu)
{
    __shared__ __half Ah[2][128][KPAD];
    __shared__ __half Al[2][128][KPAD];
    __shared__ __half Bh[2][128][KPAD];   // [n][k]
    __shared__ __half Bl[2][128][KPAD];

    const int tid  = threadIdx.x;
    const int lane = tid & 31;
    const int wid  = tid >> 5;
    const int warpM = wid & 1;
    const int warpN = wid >> 1;
    const int m0 = blockIdx.x * 128;

    const int arow = tid >> 1;
    const int akk  = (tid & 1) * 8;
    const int bn = tid & 127;
    const int bk = (tid >> 7) * 8;

    float acc[4][4][4];
#pragma unroll
    for (int i = 0; i < 4; i++)
#pragma unroll
        for (int j = 0; j < 4; j++)
#pragma unroll
            for (int q = 0; q < 4; q++) acc[i][j][q] = 0.f;

    float pa[8], pb[8];

    const int a_mrow = (lane & 7) + ((lane & 8) ? 8 : 0);
    const int a_koff = (lane & 16) ? 8 : 0;
    const int b_nrow = (lane & 7) + ((lane & 16) ? 8 : 0);
    const int b_koff = (lane & 8) ? 8 : 0;

    auto loadG = [&](int kc) {
        const int t  = kc >> 3;
        const int kk = (kc & 7) * 16;
        int m = m0 + arow;
        if (t == 0) {
            if (m < NN) {
                const float4 v0 = *(const float4*)(T.f0 + (size_t)m * W + kk + akk);
                const float4 v1 = *(const float4*)(T.f0 + (size_t)m * W + kk + akk + 4);
                pa[0] = v0.x; pa[1] = v0.y; pa[2] = v0.z; pa[3] = v0.w;
                pa[4] = v1.x; pa[5] = v1.y; pa[6] = v1.z; pa[7] = v1.w;
            } else {
#pragma unroll
                for (int j = 0; j < 8; j++) pa[j] = 0.f;
            }
        } else {
            if (m < NN) {
                uint4 qv = T.q[t - 1][(size_t)m * 16 + ((kk + akk) >> 3)];
                float rsv = T.rs[t - 1][m];
                float v0, v1, v2, v3, v4, v5, v6, v7;
                deq4(make_uint2(qv.x, qv.y), v0, v1, v2, v3);
                deq4(make_uint2(qv.z, qv.w), v4, v5, v6, v7);
                pa[0] = v0 * rsv; pa[1] = v1 * rsv; pa[2] = v2 * rsv; pa[3] = v3 * rsv;
                pa[4] = v4 * rsv; pa[5] = v5 * rsv; pa[6] = v6 * rsv; pa[7] = v7 * rsv;
            } else {
#pragma unroll
                for (int j = 0; j < 8; j++) pa[j] = 0.f;
            }
        }
        const float* Wt = Wc + t * (W * W);
#pragma unroll
        for (int j = 0; j < 8; j++) pb[j] = Wt[(kk + bk + j) * W + bn];
    };

    auto storeS = [&](int buf) {
        union { __half2 h2[4]; uint4 u; } ph, pl;
#pragma unroll
        for (int j = 0; j < 4; j++) {
            __half h0 = __float2half_rn(pa[2 * j]);
            __half h1 = __float2half_rn(pa[2 * j + 1]);
            __half l0 = __float2half_rn(pa[2 * j] - __half2float(h0));
            __half l1 = __float2half_rn(pa[2 * j + 1] - __half2float(h1));
            ph.h2[j] = __halves2half2(h0, h1);
            pl.h2[j] = __halves2half2(l0, l1);
        }
        *(uint4*)&Ah[buf][arow][akk] = ph.u;
        *(uint4*)&Al[buf][arow][akk] = pl.u;
#pragma unroll
        for (int j = 0; j < 4; j++) {
            __half h0 = __float2half_rn(pb[2 * j]);
            __half h1 = __float2half_rn(pb[2 * j + 1]);
            __half l0 = __float2half_rn(pb[2 * j] - __half2float(h0));
            __half l1 = __float2half_rn(pb[2 * j + 1] - __half2float(h1));
            ph.h2[j] = __halves2half2(h0, h1);
            pl.h2[j] = __halves2half2(l0, l1);
        }
        *(uint4*)&Bh[buf][bn][bk] = ph.u;
        *(uint4*)&Bl[buf][bn][bk] = pl.u;
    };

    loadG(0);
    storeS(0);

    for (int kc = 0; kc < 40; kc++) {
        __syncthreads();
        const int cur = kc & 1;
        const bool more = (kc + 1 < 40);
        if (more) loadG(kc + 1);

        unsigned fah[4][4], fal[4][4];
        unsigned fbh[8], fbl[8];
#pragma unroll
        for (int mt = 0; mt < 4; mt++) {
            int row = warpM * 64 + mt * 16 + a_mrow;
            unsigned ah = (unsigned)__cvta_generic_to_shared(&Ah[cur][row][a_koff]);
            unsigned al = (unsigned)__cvta_generic_to_shared(&Al[cur][row][a_koff]);
            ldm4(fah[mt], ah);
            ldm4(fal[mt], al);
        }
        {
            int n0 = warpN * 32 + b_nrow;
            int n1 = warpN * 32 + 16 + b_nrow;
            unsigned bh0 = (unsigned)__cvta_generic_to_shared(&Bh[cur][n0][b_koff]);
            unsigned bh1 = (unsigned)__cvta_generic_to_shared(&Bh[cur][n1][b_koff]);
            unsigned bl0 = (unsigned)__cvta_generic_to_shared(&Bl[cur][n0][b_koff]);
            unsigned bl1 = (unsigned)__cvta_generic_to_shared(&Bl[cur][n1][b_koff]);
            ldm4(&fbh[0], bh0);
            ldm4(&fbh[4], bh1);
            ldm4(&fbl[0], bl0);
            ldm4(&fbl[4], bl1);
        }

#pragma unroll
        for (int mt = 0; mt < 4; mt++) {
#pragma unroll
            for (int nt = 0; nt < 4; nt++) {
                mma16816(acc[mt][nt], fah[mt], fbh[2 * nt], fbh[2 * nt + 1]);
                mma16816(acc[mt][nt], fah[mt], fbl[2 * nt], fbl[2 * nt + 1]);
                mma16816(acc[mt][nt], fal[mt], fbh[2 * nt], fbh[2 * nt + 1]);
            }
        }

        if (more) storeS((kc + 1) & 1);
    }

    const int crow = lane >> 2;
    const int ccol = (lane & 3) * 2;
#pragma unroll
    for (int mt = 0; mt < 4; mt++) {
        int r = m0 + warpM * 64 + mt * 16 + crow;
#pragma unroll
        for (int nt = 0; nt < 4; nt++) {
            int c = warpN * 32 + nt * 8 + ccol;
            float b0 = bias[c], b1 = bias[c + 1];
            float v0 = acc[mt][nt][0] + b0;
            float v1 = acc[mt][nt][1] + b1;
            float v2 = acc[mt][nt][2] + b0;
            float v3 = acc[mt][nt][3] + b1;
            if (relu) {
                v0 = fmaxf(v0, 0.f); v1 = fmaxf(v1, 0.f);
                v2 = fmaxf(v2, 0.f); v3 = fmaxf(v3, 0.f);
            }
            if (r < NN)     *(float2*)(out + (size_t)r * W + c)       = make_float2(v0, v1);
            if (r + 8 < NN) *(float2*)(out + (size_t)(r + 8) * W + c) = make_float2(v2, v3);
        }
    }
}

// ---------------- last-layer telescope ----------------
__global__ void wtilde_kernel(const float* __restrict__ W5,
                              const float* __restrict__ lw)
{
    int idx = blockIdx.x * blockDim.x + threadIdx.x;
    if (idx >= 5 * W) return;
    const float* row = W5 + (size_t)idx * W;
    float s = 0.f;
    for (int o = 0; o < W; o++) s += row[o] * lw[o];
    g_WT[idx] = s;
}

__global__ void const_kernel(const float* __restrict__ cb,
                             const float* __restrict__ lw,
                             const float* __restrict__ lb)
{
    int lane = threadIdx.x & 31;
    float4 b = ((const float4*)cb)[lane];
    float4 w = ((const float4*)lw)[lane];
    float s = b.x * w.x + b.y * w.y + b.z * w.z + b.w * w.w;
#pragma unroll
    for (int off = 16; off > 0; off >>= 1)
        s += __shfl_xor_sync(0xffffffffu, s, off);
    if (lane == 0) g_c0 = s + lb[0];
}

__global__ void __launch_bounds__(256) u_kernel(
    const float* __restrict__ H, float* __restrict__ U)
{
    __shared__ float wt[5][W];
    for (int i = threadIdx.x; i < 5 * W; i += blockDim.x)
        wt[i / W][i % W] = g_WT[i];
    __syncthreads();

    int warp = (blockIdx.x * blockDim.x + threadIdx.x) >> 5;
    int lane = threadIdx.x & 31;
    if (warp >= NN) return;
    float4 hv = ((const float4*)H)[(size_t)warp * 32 + lane];
    float s[5];
#pragma unroll
    for (int k = 0; k < 5; k++) {
        float4 wv = ((const float4*)wt[k])[lane];
        float p = hv.x * wv.x + hv.y * wv.y + hv.z * wv.z + hv.w * wv.w;
#pragma unroll
        for (int off = 16; off > 0; off >>= 1)
            p += __shfl_xor_sync(0xffffffffu, p, off);
        s[k] = p;
    }
    if (lane == 0) {
        float* o = U + (size_t)warp * 8;
        o[0] = s[0]; o[1] = s[1]; o[2] = s[2]; o[3] = s[3]; o[4] = s[4];
        o[5] = 0.f;  o[6] = 0.f;  o[7] = 0.f;
    }
}

__global__ void __launch_bounds__(256) prop8_kernel(
    const float* __restrict__ U, const float* __restrict__ prev,
    float* __restrict__ out, int mode)
{
    const int l = threadIdx.x & 7;
    const int g0 = (blockIdx.x * blockDim.x + threadIdx.x) >> 3;
    const int gstride = (PROP_BLOCKS * 256) >> 3;
    for (int node = g0; node < NN; node += gstride) {
        int start = g_rowptr[node];
        int end   = g_rowptr[node + 1];
        float acc = 0.f;
        for (int i = start; i < end; i++) {
            int s = g_csr_src[i];
            float w = g_csr_w[i];
            acc += w * U[s * 8 + l];
        }
        float r = mode ? (2.f * acc - prev[node * 8 + l]) : acc;
        out[node * 8 + l] = r;
    }
}

__global__ void combine_kernel(
    const float* __restrict__ Y0, const float* __restrict__ Y1,
    const float* __restrict__ Y2, const float* __restrict__ Y3,
    const float* __restrict__ Y4, float* __restrict__ out)
{
    int j = blockIdx.x * blockDim.x + threadIdx.x;
    if (j >= NN) return;
    float s = Y0[(size_t)j * 8 + 0] + Y1[(size_t)j * 8 + 1] + Y2[(size_t)j * 8 + 2]
            + Y3[(size_t)j * 8 + 3] + Y4[(size_t)j * 8 + 4] + g_c0;
    out[j] = s;
}

// ---------------- launcher ----------------
extern "C" void kernel_launch(void* const* d_in, const int* in_sizes, int n_in,
                              void* d_out, int out_size)
{
    const float* x      = (const float*)d_in[0];
    const void*  ei     = d_in[1];
    const float* conv_w = (const float*)d_in[2];
    const float* conv_b = (const float*)d_in[3];
    const float* lin_w  = (const float*)d_in[4];
    const float* lin_b  = (const float*)d_in[5];
    float* out = (float*)d_out;

    uint2 *pT1q, *pT2q, *pT3q, *pT4q;
    float *pR1, *pR2, *pR3, *pR4;
    float *pHA, *pHB, *pU, *pY1, *pY2, *pY3, *pY4;
    cudaGetSymbolAddress((void**)&pT1q, g_T1q);
    cudaGetSymbolAddress((void**)&pT2q, g_T2q);
    cudaGetSymbolAddress((void**)&pT3q, g_T3q);
    cudaGetSymbolAddress((void**)&pT4q, g_T4q);
    cudaGetSymbolAddress((void**)&pR1, g_rs1);
    cudaGetSymbolAddress((void**)&pR2, g_rs2);
    cudaGetSymbolAddress((void**)&pR3, g_rs3);
    cudaGetSymbolAddress((void**)&pR4, g_rs4);
    cudaGetSymbolAddress((void**)&pHA, g_HA);
    cudaGetSymbolAddress((void**)&pHB, g_HB);
    cudaGetSymbolAddress((void**)&pU, g_U);
    cudaGetSymbolAddress((void**)&pY1, g_Y1);
    cudaGetSymbolAddress((void**)&pY2, g_Y2);
    cudaGetSymbolAddress((void**)&pY3, g_Y3);
    cudaGetSymbolAddress((void**)&pY4, g_Y4);

    detect_kernel<<<1, 256>>>((const int*)ei);
    init_kernel<<<NBLK, 256>>>();
    deg_kernel<<<(NE + 255) / 256, 256>>>(ei);
    dsum_kernel<<<NBLK, 256>>>();
    bscan_kernel<<<1, 256>>>();
    rowptr_kernel<<<NBLK, 256>>>();
    fill_kernel<<<(NE + 255) / 256, 256>>>(ei);
    wtilde_kernel<<<3, 256>>>(conv_w + (size_t)5 * 5 * W * W, lin_w);
    const_kernel<<<1, 32>>>(conv_b + 5 * W, lin_w, lin_b);

    const int GG = (NN + 127) / 128;

    // first 5 conv layers (all with relu)
    const float* Hin = x;
    float* Hout = pHA;
    for (int l = 0; l < 5; l++) {
        propA_kernel<<<PROP_BLOCKS, 256>>>(Hin, pT1q, pR1);
        propB_kernel<<<PROP_BLOCKS, 256>>>(pT1q, pR1, Hin, pT2q, pR2);
        propQQ_kernel<<<PROP_BLOCKS, 256>>>(pT2q, pR2, pT1q, pR1, pT3q, pR3);
        propQQ_kernel<<<PROP_BLOCKS, 256>>>(pT3q, pR3, pT2q, pR2, pT4q, pR4);
        Ptr5m T;
        T.f0 = Hin;
        T.q[0] = (const uint4*)pT1q; T.q[1] = (const uint4*)pT2q;
        T.q[2] = (const uint4*)pT3q; T.q[3] = (const uint4*)pT4q;
        T.rs[0] = pR1; T.rs[1] = pR2; T.rs[2] = pR3; T.rs[3] = pR4;
        gemm5_mma_kernel<<<GG, 256>>>(T, conv_w + (size_t)l * 5 * W * W,
                                      conv_b + l * W, Hout, 1);
        Hin = Hout;
        Hout = (Hout == pHA) ? pHB : pHA;
    }

    // telescoped last layer
    u_kernel<<<(NN + 7) / 8, 256>>>(Hin, pU);
    prop8_kernel<<<PROP_BLOCKS, 256>>>(pU, nullptr, pY1, 0);
    prop8_kernel<<<PROP_BLOCKS, 256>>>(pY1, pU, pY2, 1);
    prop8_kernel<<<PROP_BLOCKS, 256>>>(pY2, pY1, pY3, 1);
    prop8_kernel<<<PROP_BLOCKS, 256>>>(pY3, pY2, pY4, 1);
    combine_kernel<<<(NN + 255) / 256, 256>>>(pU, pY1, pY2, pY3, pY4, out);
}

// round 13
// speedup vs baseline: 1.0612x; 1.0612x over previous
#include <cuda_runtime.h>
#include <cuda_fp16.h>
#include <math.h>
#include <stdint.h>

#define NN 50000
#define NE 640000
#define W 128
#define NBLK 196   // (NN+255)/256

// ---------------- scratch (device globals: no allocation allowed) ----------------
__device__ int   g_is64;
__device__ int   g_deg[NN];
__device__ float g_dis[NN];
__device__ int   g_rowptr[NN + 1];
__device__ int   g_fill[NN];
__device__ int2  g_csr[NE];          // {src, w bits}
__device__ int   g_bsum[NBLK];
__device__ int   g_boff[NBLK];

__device__ float g_P1[(size_t)NN * W];
__device__ float g_P2[(size_t)NN * W];
__device__ float g_P3[(size_t)NN * W];
__device__ float g_P4[(size_t)NN * W];
__device__ float g_HA[(size_t)NN * W];
__device__ float g_HB[(size_t)NN * W];

// power-basis transformed conv weights for layers 0..4
__device__ float g_WMOD[(size_t)5 * 5 * W * W];

__device__ float g_U [(size_t)NN * 8];
__device__ float g_Y1[(size_t)NN * 8];
__device__ float g_Y2[(size_t)NN * 8];
__device__ float g_Y3[(size_t)NN * 8];
__device__ float g_Y4[(size_t)NN * 8];
__device__ float g_WT[5 * W];
__device__ float g_c0;

// ---------------- dtype detection ----------------
__global__ void detect_kernel(const int* __restrict__ ei) {
    __shared__ int any;
    if (threadIdx.x == 0) any = 0;
    __syncthreads();
    for (int i = threadIdx.x; i < 4096; i += blockDim.x)
        if (ei[2 * i + 1] != 0) any = 1;
    __syncthreads();
    if (threadIdx.x == 0) g_is64 = (any == 0) ? 1 : 0;
}

__device__ __forceinline__ int load_edge(const void* ei, long long idx, int is64) {
    if (is64) return (int)((const long long*)ei)[idx];
    return ((const int*)ei)[idx];
}

// ---------------- CSR build ----------------
__global__ void init_kernel() {
    int i = blockIdx.x * blockDim.x + threadIdx.x;
    if (i < NN) { g_deg[i] = 0; g_fill[i] = 0; }
}

__global__ void deg_kernel(const void* __restrict__ ei) {
    int e = blockIdx.x * blockDim.x + threadIdx.x;
    if (e >= NE) return;
    int is64 = g_is64;
    int d = load_edge(ei, (long long)NE + e, is64);
    atomicAdd(&g_deg[d], 1);
}

__global__ void dsum_kernel() {
    __shared__ int sdata[256];
    int t = threadIdx.x;
    int i = blockIdx.x * 256 + t;
    int d = (i < NN) ? g_deg[i] : 0;
    if (i < NN) g_dis[i] = (d > 0) ? rsqrtf((float)d) : 0.0f;
    sdata[t] = d;
    __syncthreads();
    for (int s = 128; s > 0; s >>= 1) {
        if (t < s) sdata[t] += sdata[t + s];
        __syncthreads();
    }
    if (t == 0) g_bsum[blockIdx.x] = sdata[0];
}

__global__ void bscan_kernel() {
    __shared__ int s[256];
    int t = threadIdx.x;
    int v = (t < NBLK) ? g_bsum[t] : 0;
    s[t] = v;
    __syncthreads();
    for (int off = 1; off < 256; off <<= 1) {
        int u = (t >= off) ? s[t - off] : 0;
        __syncthreads();
        s[t] += u;
        __syncthreads();
    }
    if (t < NBLK) g_boff[t] = (t == 0) ? 0 : s[t - 1];
}

__global__ void rowptr_kernel() {
    __shared__ int s[256];
    int t = threadIdx.x;
    int i = blockIdx.x * 256 + t;
    int d = (i < NN) ? g_deg[i] : 0;
    s[t] = d;
    __syncthreads();
    for (int off = 1; off < 256; off <<= 1) {
        int u = (t >= off) ? s[t - off] : 0;
        __syncthreads();
        s[t] += u;
        __syncthreads();
    }
    if (i < NN) g_rowptr[i] = g_boff[blockIdx.x] + s[t] - d;
    if (i == NN - 1) g_rowptr[NN] = NE;
}

__global__ void fill_kernel(const void* __restrict__ ei) {
    int e = blockIdx.x * blockDim.x + threadIdx.x;
    if (e >= NE) return;
    int is64 = g_is64;
    int s = load_edge(ei, e, is64);
    int d = load_edge(ei, (long long)NE + e, is64);
    int pos = atomicAdd(&g_fill[d], 1);
    int idx = g_rowptr[d] + pos;
    float w = -g_dis[s] * g_dis[d];
    g_csr[idx] = make_int2(s, __float_as_int(w));
}

// ---------------- weight transform to power basis (layers 0..4) ----------------
// W^0 = W0 - W2 + W4 ; W^1 = W1 - 3W3 ; W^2 = 2W2 - 8W4 ; W^3 = 4W3 ; W^4 = 8W4
__global__ void wmod_kernel(const float* __restrict__ conv_w) {
    int gid = blockIdx.x * blockDim.x + threadIdx.x;
    if (gid >= 5 * W * W) return;
    int l = gid / (W * W);
    int e = gid % (W * W);
    const float* Wl = conv_w + (size_t)l * 5 * W * W;
    float w0 = Wl[0 * W * W + e];
    float w1 = Wl[1 * W * W + e];
    float w2 = Wl[2 * W * W + e];
    float w3 = Wl[3 * W * W + e];
    float w4 = Wl[4 * W * W + e];
    float* O = g_WMOD + (size_t)l * 5 * W * W;
    O[0 * W * W + e] = w0 - w2 + w4;
    O[1 * W * W + e] = w1 - 3.f * w3;
    O[2 * W * W + e] = 2.f * w2 - 8.f * w4;
    O[3 * W * W + e] = 4.f * w3;
    O[4 * W * W + e] = 8.f * w4;
}

// ---------------- propagate: out = L @ X (persistent grid-stride, fp32) --------
#define PROP_BLOCKS 1184   // 148 SMs * 8 CTAs

__global__ void __launch_bounds__(256) propagate_kernel(
    const float* __restrict__ X, float* __restrict__ out)
{
    const int lane = threadIdx.x & 31;
    const int warp0 = (blockIdx.x * blockDim.x + threadIdx.x) >> 5;
    const int wstride = (PROP_BLOCKS * 256) >> 5;   // 9472
    const float4* X4 = (const float4*)X;

    for (int node = warp0; node < NN; node += wstride) {
        int start = g_rowptr[node];
        int end   = g_rowptr[node + 1];
        float4 acc = make_float4(0.f, 0.f, 0.f, 0.f);
        int i = start;
        for (; i + 1 < end; i += 2) {
            int2 e0 = g_csr[i];
            int2 e1 = g_csr[i + 1];
            float w0 = __int_as_float(e0.y);
            float w1 = __int_as_float(e1.y);
            float4 v0 = X4[(size_t)e0.x * 32 + lane];
            float4 v1 = X4[(size_t)e1.x * 32 + lane];
            acc.x += w0 * v0.x; acc.y += w0 * v0.y; acc.z += w0 * v0.z; acc.w += w0 * v0.w;
            acc.x += w1 * v1.x; acc.y += w1 * v1.y; acc.z += w1 * v1.z; acc.w += w1 * v1.w;
        }
        if (i < end) {
            int2 e0 = g_csr[i];
            float w0 = __int_as_float(e0.y);
            float4 v0 = X4[(size_t)e0.x * 32 + lane];
            acc.x += w0 * v0.x; acc.y += w0 * v0.y; acc.z += w0 * v0.z; acc.w += w0 * v0.w;
        }
        ((float4*)out)[(size_t)node * 32 + lane] = acc;
    }
}

// ---------------- tensor-core fused 5-term GEMM (split-fp16, fp32-grade) --------
struct Ptr5 { const float* p[5]; };

#define KPAD 24

__device__ __forceinline__ void mma16816(float c[4], const unsigned a[4], const unsigned b0, const unsigned b1) {
    asm volatile(
        "mma.sync.aligned.m16n8k16.row.col.f32.f16.f16.f32 "
        "{%0,%1,%2,%3}, {%4,%5,%6,%7}, {%8,%9}, {%0,%1,%2,%3};"
        : "+f"(c[0]), "+f"(c[1]), "+f"(c[2]), "+f"(c[3])
        : "r"(a[0]), "r"(a[1]), "r"(a[2]), "r"(a[3]), "r"(b0), "r"(b1));
}

__device__ __forceinline__ void ldm4(unsigned r[4], unsigned addr) {
    asm volatile("ldmatrix.sync.aligned.m8n8.x4.shared.b16 {%0,%1,%2,%3}, [%4];"
        : "=r"(r[0]), "=r"(r[1]), "=r"(r[2]), "=r"(r[3]) : "r"(addr));
}

__global__ void __launch_bounds__(256) gemm5_mma_kernel(
    Ptr5 T, const float* __restrict__ Wc, const float* __restrict__ bias,
    float* __restrict__ out, int relu)
{
    __shared__ __half Ah[2][128][KPAD];
    __shared__ __half Al[2][128][KPAD];
    __shared__ __half Bh[2][128][KPAD];   // [n][k]
    __shared__ __half Bl[2][128][KPAD];

    const int tid  = threadIdx.x;
    const int lane = tid & 31;
    const int wid  = tid >> 5;
    const int warpM = wid & 1;
    const int warpN = wid >> 1;
    const int m0 = blockIdx.x * 128;

    const int arow = tid >> 1;
    const int akk  = (tid & 1) * 8;
    const int bn = tid & 127;
    const int bk = (tid >> 7) * 8;

    float acc[4][4][4];
#pragma unroll
    for (int i = 0; i < 4; i++)
#pragma unroll
        for (int j = 0; j < 4; j++)
#pragma unroll
            for (int q = 0; q < 4; q++) acc[i][j][q] = 0.f;

    float pa[8], pb[8];

    const int a_mrow = (lane & 7) + ((lane & 8) ? 8 : 0);
    const int a_koff = (lane & 16) ? 8 : 0;
    const int b_nrow = (lane & 7) + ((lane & 16) ? 8 : 0);
    const int b_koff = (lane & 8) ? 8 : 0;

    auto loadG = [&](int kc) {
        const int t  = kc >> 3;
        const int kk = (kc & 7) * 16;
        const float* A = T.p[t];
        int m = m0 + arow;
        if (m < NN) {
            const float4 v0 = *(const float4*)(A + (size_t)m * W + kk + akk);
            const float4 v1 = *(const float4*)(A + (size_t)m * W + kk + akk + 4);
            pa[0] = v0.x; pa[1] = v0.y; pa[2] = v0.z; pa[3] = v0.w;
            pa[4] = v1.x; pa[5] = v1.y; pa[6] = v1.z; pa[7] = v1.w;
        } else {
#pragma unroll
            for (int j = 0; j < 8; j++) pa[j] = 0.f;
        }
        const float* Wt = Wc + t * (W * W);
#pragma unroll
        for (int j = 0; j < 8; j++) pb[j] = Wt[(kk + bk + j) * W + bn];
    };

    auto storeS = [&](int buf) {
        union { __half2 h2[4]; uint4 u; } ph, pl;
#pragma unroll
        for (int j = 0; j < 4; j++) {
            __half h0 = __float2half_rn(pa[2 * j]);
            __half h1 = __float2half_rn(pa[2 * j + 1]);
            __half l0 = __float2half_rn(pa[2 * j] - __half2float(h0));
            __half l1 = __float2half_rn(pa[2 * j + 1] - __half2float(h1));
            ph.h2[j] = __halves2half2(h0, h1);
            pl.h2[j] = __halves2half2(l0, l1);
        }
        *(uint4*)&Ah[buf][arow][akk] = ph.u;
        *(uint4*)&Al[buf][arow][akk] = pl.u;
#pragma unroll
        for (int j = 0; j < 4; j++) {
            __half h0 = __float2half_rn(pb[2 * j]);
            __half h1 = __float2half_rn(pb[2 * j + 1]);
            __half l0 = __float2half_rn(pb[2 * j] - __half2float(h0));
            __half l1 = __float2half_rn(pb[2 * j + 1] - __half2float(h1));
            ph.h2[j] = __halves2half2(h0, h1);
            pl.h2[j] = __halves2half2(l0, l1);
        }
        *(uint4*)&Bh[buf][bn][bk] = ph.u;
        *(uint4*)&Bl[buf][bn][bk] = pl.u;
    };

    loadG(0);
    storeS(0);

    for (int kc = 0; kc < 40; kc++) {
        __syncthreads();
        const int cur = kc & 1;
        const bool more = (kc + 1 < 40);
        if (more) loadG(kc + 1);

        unsigned fah[4][4], fal[4][4];
        unsigned fbh[8], fbl[8];
#pragma unroll
        for (int mt = 0; mt < 4; mt++) {
            int row = warpM * 64 + mt * 16 + a_mrow;
            unsigned ah = (unsigned)__cvta_generic_to_shared(&Ah[cur][row][a_koff]);
            unsigned al = (unsigned)__cvta_generic_to_shared(&Al[cur][row][a_koff]);
            ldm4(fah[mt], ah);
            ldm4(fal[mt], al);
        }
        {
            int n0 = warpN * 32 + b_nrow;
            int n1 = warpN * 32 + 16 + b_nrow;
            unsigned bh0 = (unsigned)__cvta_generic_to_shared(&Bh[cur][n0][b_koff]);
            unsigned bh1 = (unsigned)__cvta_generic_to_shared(&Bh[cur][n1][b_koff]);
            unsigned bl0 = (unsigned)__cvta_generic_to_shared(&Bl[cur][n0][b_koff]);
            unsigned bl1 = (unsigned)__cvta_generic_to_shared(&Bl[cur][n1][b_koff]);
            ldm4(&fbh[0], bh0);
            ldm4(&fbh[4], bh1);
            ldm4(&fbl[0], bl0);
            ldm4(&fbl[4], bl1);
        }

#pragma unroll
        for (int mt = 0; mt < 4; mt++) {
#pragma unroll
            for (int nt = 0; nt < 4; nt++) {
                mma16816(acc[mt][nt], fah[mt], fbh[2 * nt], fbh[2 * nt + 1]);
                mma16816(acc[mt][nt], fah[mt], fbl[2 * nt], fbl[2 * nt + 1]);
                mma16816(acc[mt][nt], fal[mt], fbh[2 * nt], fbh[2 * nt + 1]);
            }
        }

        if (more) storeS((kc + 1) & 1);
    }

    const int crow = lane >> 2;
    const int ccol = (lane & 3) * 2;
#pragma unroll
    for (int mt = 0; mt < 4; mt++) {
        int r = m0 + warpM * 64 + mt * 16 + crow;
#pragma unroll
        for (int nt = 0; nt < 4; nt++) {
            int c = warpN * 32 + nt * 8 + ccol;
            float b0 = bias[c], b1 = bias[c + 1];
            float v0 = acc[mt][nt][0] + b0;
            float v1 = acc[mt][nt][1] + b1;
            float v2 = acc[mt][nt][2] + b0;
            float v3 = acc[mt][nt][3] + b1;
            if (relu) {
                v0 = fmaxf(v0, 0.f); v1 = fmaxf(v1, 0.f);
                v2 = fmaxf(v2, 0.f); v3 = fmaxf(v3, 0.f);
            }
            if (r < NN)     *(float2*)(out + (size_t)r * W + c)       = make_float2(v0, v1);
            if (r + 8 < NN) *(float2*)(out + (size_t)(r + 8) * W + c) = make_float2(v2, v3);
        }
    }
}

// ---------------- last-layer telescope ----------------
__global__ void wtilde_kernel(const float* __restrict__ W5,
                              const float* __restrict__ lw)
{
    int idx = blockIdx.x * blockDim.x + threadIdx.x;
    if (idx >= 5 * W) return;
    const float* row = W5 + (size_t)idx * W;
    float s = 0.f;
    for (int o = 0; o < W; o++) s += row[o] * lw[o];
    g_WT[idx] = s;
}

// transform w~ to power basis (in place)
__global__ void wt_transform_kernel() {
    int in = threadIdx.x;
    if (in >= W) return;
    float w0 = g_WT[0 * W + in];
    float w1 = g_WT[1 * W + in];
    float w2 = g_WT[2 * W + in];
    float w3 = g_WT[3 * W + in];
    float w4 = g_WT[4 * W + in];
    g_WT[0 * W + in] = w0 - w2 + w4;
    g_WT[1 * W + in] = w1 - 3.f * w3;
    g_WT[2 * W + in] = 2.f * w2 - 8.f * w4;
    g_WT[3 * W + in] = 4.f * w3;
    g_WT[4 * W + in] = 8.f * w4;
}

__global__ void const_kernel(const float* __restrict__ cb,
                             const float* __restrict__ lw,
                             const float* __restrict__ lb)
{
    int lane = threadIdx.x & 31;
    float4 b = ((const float4*)cb)[lane];
    float4 w = ((const float4*)lw)[lane];
    float s = b.x * w.x + b.y * w.y + b.z * w.z + b.w * w.w;
#pragma unroll
    for (int off = 16; off > 0; off >>= 1)
        s += __shfl_xor_sync(0xffffffffu, s, off);
    if (lane == 0) g_c0 = s + lb[0];
}

__global__ void __launch_bounds__(256) u_kernel(
    const float* __restrict__ H, float* __restrict__ U)
{
    __shared__ float wt[5][W];
    for (int i = threadIdx.x; i < 5 * W; i += blockDim.x)
        wt[i / W][i % W] = g_WT[i];
    __syncthreads();

    int warp = (blockIdx.x * blockDim.x + threadIdx.x) >> 5;
    int lane = threadIdx.x & 31;
    if (warp >= NN) return;
    float4 hv = ((const float4*)H)[(size_t)warp * 32 + lane];
    float s[5];
#pragma unroll
    for (int k = 0; k < 5; k++) {
        float4 wv = ((const float4*)wt[k])[lane];
        float p = hv.x * wv.x + hv.y * wv.y + hv.z * wv.z + hv.w * wv.w;
#pragma unroll
        for (int off = 16; off > 0; off >>= 1)
            p += __shfl_xor_sync(0xffffffffu, p, off);
        s[k] = p;
    }
    if (lane == 0) {
        float* o = U + (size_t)warp * 8;
        o[0] = s[0]; o[1] = s[1]; o[2] = s[2]; o[3] = s[3]; o[4] = s[4];
        o[5] = 0.f;  o[6] = 0.f;  o[7] = 0.f;
    }
}

// width-8 propagate: out = L @ U (power basis, no prev)
__global__ void __launch_bounds__(256) prop8_kernel(
    const float* __restrict__ U, float* __restrict__ out)
{
    const int l = threadIdx.x & 7;
    const int g0 = (blockIdx.x * blockDim.x + threadIdx.x) >> 3;
    const int gstride = (PROP_BLOCKS * 256) >> 3;
    for (int node = g0; node < NN; node += gstride) {
        int start = g_rowptr[node];
        int end   = g_rowptr[node + 1];
        float acc = 0.f;
        for (int i = start; i < end; i++) {
            int2 e = g_csr[i];
            acc += __int_as_float(e.y) * U[e.x * 8 + l];
        }
        out[node * 8 + l] = acc;
    }
}

__global__ void combine_kernel(
    const float* __restrict__ Y0, const float* __restrict__ Y1,
    const float* __restrict__ Y2, const float* __restrict__ Y3,
    const float* __restrict__ Y4, float* __restrict__ out)
{
    int j = blockIdx.x * blockDim.x + threadIdx.x;
    if (j >= NN) return;
    float s = Y0[(size_t)j * 8 + 0] + Y1[(size_t)j * 8 + 1] + Y2[(size_t)j * 8 + 2]
            + Y3[(size_t)j * 8 + 3] + Y4[(size_t)j * 8 + 4] + g_c0;
    out[j] = s;
}

// ---------------- launcher ----------------
extern "C" void kernel_launch(void* const* d_in, const int* in_sizes, int n_in,
                              void* d_out, int out_size)
{
    const float* x      = (const float*)d_in[0];
    const void*  ei     = d_in[1];
    const float* conv_w = (const float*)d_in[2];
    const float* conv_b = (const float*)d_in[3];
    const float* lin_w  = (const float*)d_in[4];
    const float* lin_b  = (const float*)d_in[5];
    float* out = (float*)d_out;

    float *pP1, *pP2, *pP3, *pP4, *pHA, *pHB, *pWM, *pU, *pY1, *pY2, *pY3, *pY4;
    cudaGetSymbolAddress((void**)&pP1, g_P1);
    cudaGetSymbolAddress((void**)&pP2, g_P2);
    cudaGetSymbolAddress((void**)&pP3, g_P3);
    cudaGetSymbolAddress((void**)&pP4, g_P4);
    cudaGetSymbolAddress((void**)&pHA, g_HA);
    cudaGetSymbolAddress((void**)&pHB, g_HB);
    cudaGetSymbolAddress((void**)&pWM, g_WMOD);
    cudaGetSymbolAddress((void**)&pU, g_U);
    cudaGetSymbolAddress((void**)&pY1, g_Y1);
    cudaGetSymbolAddress((void**)&pY2, g_Y2);
    cudaGetSymbolAddress((void**)&pY3, g_Y3);
    cudaGetSymbolAddress((void**)&pY4, g_Y4);

    detect_kernel<<<1, 256>>>((const int*)ei);
    init_kernel<<<NBLK, 256>>>();
    deg_kernel<<<(NE + 255) / 256, 256>>>(ei);
    dsum_kernel<<<NBLK, 256>>>();
    bscan_kernel<<<1, 256>>>();
    rowptr_kernel<<<NBLK, 256>>>();
    fill_kernel<<<(NE + 255) / 256, 256>>>(ei);
    wmod_kernel<<<(5 * W * W + 255) / 256, 256>>>(conv_w);
    wtilde_kernel<<<3, 256>>>(conv_w + (size_t)5 * 5 * W * W, lin_w);
    wt_transform_kernel<<<1, 128>>>();
    const_kernel<<<1, 32>>>(conv_b + 5 * W, lin_w, lin_b);

    const int GG = (NN + 127) / 128;

    // first 5 conv layers (all with relu); power basis: Pk = L @ P(k-1)
    const float* Hin = x;
    float* Hout = pHA;
    for (int l = 0; l < 5; l++) {
        propagate_kernel<<<PROP_BLOCKS, 256>>>(Hin, pP1);
        propagate_kernel<<<PROP_BLOCKS, 256>>>(pP1, pP2);
        propagate_kernel<<<PROP_BLOCKS, 256>>>(pP2, pP3);
        propagate_kernel<<<PROP_BLOCKS, 256>>>(pP3, pP4);
        Ptr5 T;
        T.p[0] = Hin; T.p[1] = pP1; T.p[2] = pP2; T.p[3] = pP3; T.p[4] = pP4;
        gemm5_mma_kernel<<<GG, 256>>>(T, pWM + (size_t)l * 5 * W * W,
                                      conv_b + l * W, Hout, 1);
        Hin = Hout;
        Hout = (Hout == pHA) ? pHB : pHA;
    }

    // telescoped last layer (power basis)
    u_kernel<<<(NN + 7) / 8, 256>>>(Hin, pU);
    prop8_kernel<<<PROP_BLOCKS, 256>>>(pU, pY1);
    prop8_kernel<<<PROP_BLOCKS, 256>>>(pY1, pY2);
    prop8_kernel<<<PROP_BLOCKS, 256>>>(pY2, pY3);
    prop8_kernel<<<PROP_BLOCKS, 256>>>(pY3, pY4);
    combine_kernel<<<(NN + 255) / 256, 256>>>(pU, pY1, pY2, pY3, pY4, out);
}

// round 14
// speedup vs baseline: 1.2177x; 1.1475x over previous
#include <cuda_runtime.h>
#include <cuda_fp16.h>
#include <math.h>
#include <stdint.h>

#define NN 50000
#define NE 640000
#define W 128
#define NBLK 196   // (NN+255)/256

// ---------------- scratch (device globals: no allocation allowed) ----------------
__device__ int   g_is64;
__device__ int   g_deg[NN];
__device__ float g_dis[NN];
__device__ int   g_rowptr[NN + 1];
__device__ int   g_fill[NN];
__device__ int   g_csr_src[NE];
__device__ float g_csr_w[NE];
__device__ int   g_bsum[NBLK];
__device__ int   g_boff[NBLK];

__device__ float g_P1[(size_t)NN * W];
__device__ float g_P2[(size_t)NN * W];
__device__ float g_P3[(size_t)NN * W];
__device__ float g_P4[(size_t)NN * W];
__device__ float g_HA[(size_t)NN * W];
__device__ float g_HB[(size_t)NN * W];

// power-basis transformed conv weights for layers 0..4
__device__ float g_WMOD[(size_t)5 * 5 * W * W];

__device__ float g_U [(size_t)NN * 8];
__device__ float g_Y1[(size_t)NN * 8];
__device__ float g_Y2[(size_t)NN * 8];
__device__ float g_Y3[(size_t)NN * 8];
__device__ float g_Y4[(size_t)NN * 8];
__device__ float g_WT[5 * W];
__device__ float g_c0;

// ---------------- dtype detection ----------------
__global__ void detect_kernel(const int* __restrict__ ei) {
    __shared__ int any;
    if (threadIdx.x == 0) any = 0;
    __syncthreads();
    for (int i = threadIdx.x; i < 4096; i += blockDim.x)
        if (ei[2 * i + 1] != 0) any = 1;
    __syncthreads();
    if (threadIdx.x == 0) g_is64 = (any == 0) ? 1 : 0;
}

__device__ __forceinline__ int load_edge(const void* ei, long long idx, int is64) {
    if (is64) return (int)((const long long*)ei)[idx];
    return ((const int*)ei)[idx];
}

// ---------------- CSR build ----------------
__global__ void init_kernel() {
    int i = blockIdx.x * blockDim.x + threadIdx.x;
    if (i < NN) { g_deg[i] = 0; g_fill[i] = 0; }
}

__global__ void deg_kernel(const void* __restrict__ ei) {
    int e = blockIdx.x * blockDim.x + threadIdx.x;
    if (e >= NE) return;
    int is64 = g_is64;
    int d = load_edge(ei, (long long)NE + e, is64);
    atomicAdd(&g_deg[d], 1);
}

__global__ void dsum_kernel() {
    __shared__ int sdata[256];
    int t = threadIdx.x;
    int i = blockIdx.x * 256 + t;
    int d = (i < NN) ? g_deg[i] : 0;
    if (i < NN) g_dis[i] = (d > 0) ? rsqrtf((float)d) : 0.0f;
    sdata[t] = d;
    __syncthreads();
    for (int s = 128; s > 0; s >>= 1) {
        if (t < s) sdata[t] += sdata[t + s];
        __syncthreads();
    }
    if (t == 0) g_bsum[blockIdx.x] = sdata[0];
}

__global__ void bscan_kernel() {
    __shared__ int s[256];
    int t = threadIdx.x;
    int v = (t < NBLK) ? g_bsum[t] : 0;
    s[t] = v;
    __syncthreads();
    for (int off = 1; off < 256; off <<= 1) {
        int u = (t >= off) ? s[t - off] : 0;
        __syncthreads();
        s[t] += u;
        __syncthreads();
    }
    if (t < NBLK) g_boff[t] = (t == 0) ? 0 : s[t - 1];
}

__global__ void rowptr_kernel() {
    __shared__ int s[256];
    int t = threadIdx.x;
    int i = blockIdx.x * 256 + t;
    int d = (i < NN) ? g_deg[i] : 0;
    s[t] = d;
    __syncthreads();
    for (int off = 1; off < 256; off <<= 1) {
        int u = (t >= off) ? s[t - off] : 0;
        __syncthreads();
        s[t] += u;
        __syncthreads();
    }
    if (i < NN) g_rowptr[i] = g_boff[blockIdx.x] + s[t] - d;
    if (i == NN - 1) g_rowptr[NN] = NE;
}

__global__ void fill_kernel(const void* __restrict__ ei) {
    int e = blockIdx.x * blockDim.x + threadIdx.x;
    if (e >= NE) return;
    int is64 = g_is64;
    int s = load_edge(ei, e, is64);
    int d = load_edge(ei, (long long)NE + e, is64);
    int pos = atomicAdd(&g_fill[d], 1);
    int idx = g_rowptr[d] + pos;
    g_csr_src[idx] = s;
    g_csr_w[idx]   = -g_dis[s] * g_dis[d];
}

// ---------------- weight transform to power basis (layers 0..4) ----------------
__global__ void wmod_kernel(const float* __restrict__ conv_w) {
    int gid = blockIdx.x * blockDim.x + threadIdx.x;
    if (gid >= 5 * W * W) return;
    int l = gid / (W * W);
    int e = gid % (W * W);
    const float* Wl = conv_w + (size_t)l * 5 * W * W;
    float w0 = Wl[0 * W * W + e];
    float w1 = Wl[1 * W * W + e];
    float w2 = Wl[2 * W * W + e];
    float w3 = Wl[3 * W * W + e];
    float w4 = Wl[4 * W * W + e];
    float* O = g_WMOD + (size_t)l * 5 * W * W;
    O[0 * W * W + e] = w0 - w2 + w4;
    O[1 * W * W + e] = w1 - 3.f * w3;
    O[2 * W * W + e] = 2.f * w2 - 8.f * w4;
    O[3 * W * W + e] = 4.f * w3;
    O[4 * W * W + e] = 8.f * w4;
}

// ---------------- propagate: out = L @ X (r10-exact body, no prev) -------------
#define PROP_BLOCKS 1184   // 148 SMs * 8 CTAs

__global__ void __launch_bounds__(256) propagate_kernel(
    const float* __restrict__ X, float* __restrict__ out)
{
    const int lane = threadIdx.x & 31;
    const int warp0 = (blockIdx.x * blockDim.x + threadIdx.x) >> 5;
    const int wstride = (PROP_BLOCKS * 256) >> 5;   // 9472
    const float4* X4 = (const float4*)X;

    for (int node = warp0; node < NN; node += wstride) {
        int start = g_rowptr[node];
        int end   = g_rowptr[node + 1];
        float4 acc = make_float4(0.f, 0.f, 0.f, 0.f);
        int i = start;
        for (; i + 1 < end; i += 2) {
            int s0 = g_csr_src[i];     float w0 = g_csr_w[i];
            int s1 = g_csr_src[i + 1]; float w1 = g_csr_w[i + 1];
            float4 v0 = X4[(size_t)s0 * 32 + lane];
            float4 v1 = X4[(size_t)s1 * 32 + lane];
            acc.x += w0 * v0.x; acc.y += w0 * v0.y; acc.z += w0 * v0.z; acc.w += w0 * v0.w;
            acc.x += w1 * v1.x; acc.y += w1 * v1.y; acc.z += w1 * v1.z; acc.w += w1 * v1.w;
        }
        if (i < end) {
            int s0 = g_csr_src[i]; float w0 = g_csr_w[i];
            float4 v0 = X4[(size_t)s0 * 32 + lane];
            acc.x += w0 * v0.x; acc.y += w0 * v0.y; acc.z += w0 * v0.z; acc.w += w0 * v0.w;
        }
        ((float4*)out)[(size_t)node * 32 + lane] = acc;
    }
}

// ---------------- tensor-core fused 5-term GEMM (split-fp16, fp32-grade) --------
struct Ptr5 { const float* p[5]; };

#define KPAD 24

__device__ __forceinline__ void mma16816(float c[4], const unsigned a[4], const unsigned b0, const unsigned b1) {
    asm volatile(
        "mma.sync.aligned.m16n8k16.row.col.f32.f16.f16.f32 "
        "{%0,%1,%2,%3}, {%4,%5,%6,%7}, {%8,%9}, {%0,%1,%2,%3};"
        : "+f"(c[0]), "+f"(c[1]), "+f"(c[2]), "+f"(c[3])
        : "r"(a[0]), "r"(a[1]), "r"(a[2]), "r"(a[3]), "r"(b0), "r"(b1));
}

__device__ __forceinline__ void ldm4(unsigned r[4], unsigned addr) {
    asm volatile("ldmatrix.sync.aligned.m8n8.x4.shared.b16 {%0,%1,%2,%3}, [%4];"
        : "=r"(r[0]), "=r"(r[1]), "=r"(r[2]), "=r"(r[3]) : "r"(addr));
}

__global__ void __launch_bounds__(256) gemm5_mma_kernel(
    Ptr5 T, const float* __restrict__ Wc, const float* __restrict__ bias,
    float* __restrict__ out, int relu)
{
    __shared__ __half Ah[2][128][KPAD];
    __shared__ __half Al[2][128][KPAD];
    __shared__ __half Bh[2][128][KPAD];   // [n][k]
    __shared__ __half Bl[2][128][KPAD];

    const int tid  = threadIdx.x;
    const int lane = tid & 31;
    const int wid  = tid >> 5;
    const int warpM = wid & 1;
    const int warpN = wid >> 1;
    const int m0 = blockIdx.x * 128;

    const int arow = tid >> 1;
    const int akk  = (tid & 1) * 8;
    const int bn = tid & 127;
    const int bk = (tid >> 7) * 8;

    float acc[4][4][4];
#pragma unroll
    for (int i = 0; i < 4; i++)
#pragma unroll
        for (int j = 0; j < 4; j++)
#pragma unroll
            for (int q = 0; q < 4; q++) acc[i][j][q] = 0.f;

    float pa[8], pb[8];

    const int a_mrow = (lane & 7) + ((lane & 8) ? 8 : 0);
    const int a_koff = (lane & 16) ? 8 : 0;
    const int b_nrow = (lane & 7) + ((lane & 16) ? 8 : 0);
    const int b_koff = (lane & 8) ? 8 : 0;

    auto loadG = [&](int kc) {
        const int t  = kc >> 3;
        const int kk = (kc & 7) * 16;
        const float* A = T.p[t];
        int m = m0 + arow;
        if (m < NN) {
            const float4 v0 = *(const float4*)(A + (size_t)m * W + kk + akk);
            const float4 v1 = *(const float4*)(A + (size_t)m * W + kk + akk + 4);
            pa[0] = v0.x; pa[1] = v0.y; pa[2] = v0.z; pa[3] = v0.w;
            pa[4] = v1.x; pa[5] = v1.y; pa[6] = v1.z; pa[7] = v1.w;
        } else {
#pragma unroll
            for (int j = 0; j < 8; j++) pa[j] = 0.f;
        }
        const float* Wt = Wc + t * (W * W);
#pragma unroll
        for (int j = 0; j < 8; j++) pb[j] = Wt[(kk + bk + j) * W + bn];
    };

    auto storeS = [&](int buf) {
        union { __half2 h2[4]; uint4 u; } ph, pl;
#pragma unroll
        for (int j = 0; j < 4; j++) {
            __half h0 = __float2half_rn(pa[2 * j]);
            __half h1 = __float2half_rn(pa[2 * j + 1]);
            __half l0 = __float2half_rn(pa[2 * j] - __half2float(h0));
            __half l1 = __float2half_rn(pa[2 * j + 1] - __half2float(h1));
            ph.h2[j] = __halves2half2(h0, h1);
            pl.h2[j] = __halves2half2(l0, l1);
        }
        *(uint4*)&Ah[buf][arow][akk] = ph.u;
        *(uint4*)&Al[buf][arow][akk] = pl.u;
#pragma unroll
        for (int j = 0; j < 4; j++) {
            __half h0 = __float2half_rn(pb[2 * j]);
            __half h1 = __float2half_rn(pb[2 * j + 1]);
            __half l0 = __float2half_rn(pb[2 * j] - __half2float(h0));
            __half l1 = __float2half_rn(pb[2 * j + 1] - __half2float(h1));
            ph.h2[j] = __halves2half2(h0, h1);
            pl.h2[j] = __halves2half2(l0, l1);
        }
        *(uint4*)&Bh[buf][bn][bk] = ph.u;
        *(uint4*)&Bl[buf][bn][bk] = pl.u;
    };

    loadG(0);
    storeS(0);

    for (int kc = 0; kc < 40; kc++) {
        __syncthreads();
        const int cur = kc & 1;
        const bool more = (kc + 1 < 40);
        if (more) loadG(kc + 1);

        unsigned fah[4][4], fal[4][4];
        unsigned fbh[8], fbl[8];
#pragma unroll
        for (int mt = 0; mt < 4; mt++) {
            int row = warpM * 64 + mt * 16 + a_mrow;
            unsigned ah = (unsigned)__cvta_generic_to_shared(&Ah[cur][row][a_koff]);
            unsigned al = (unsigned)__cvta_generic_to_shared(&Al[cur][row][a_koff]);
            ldm4(fah[mt], ah);
            ldm4(fal[mt], al);
        }
        {
            int n0 = warpN * 32 + b_nrow;
            int n1 = warpN * 32 + 16 + b_nrow;
            unsigned bh0 = (unsigned)__cvta_generic_to_shared(&Bh[cur][n0][b_koff]);
            unsigned bh1 = (unsigned)__cvta_generic_to_shared(&Bh[cur][n1][b_koff]);
            unsigned bl0 = (unsigned)__cvta_generic_to_shared(&Bl[cur][n0][b_koff]);
            unsigned bl1 = (unsigned)__cvta_generic_to_shared(&Bl[cur][n1][b_koff]);
            ldm4(&fbh[0], bh0);
            ldm4(&fbh[4], bh1);
            ldm4(&fbl[0], bl0);
            ldm4(&fbl[4], bl1);
        }

#pragma unroll
        for (int mt = 0; mt < 4; mt++) {
#pragma unroll
            for (int nt = 0; nt < 4; nt++) {
                mma16816(acc[mt][nt], fah[mt], fbh[2 * nt], fbh[2 * nt + 1]);
                mma16816(acc[mt][nt], fah[mt], fbl[2 * nt], fbl[2 * nt + 1]);
                mma16816(acc[mt][nt], fal[mt], fbh[2 * nt], fbh[2 * nt + 1]);
            }
        }

        if (more) storeS((kc + 1) & 1);
    }

    const int crow = lane >> 2;
    const int ccol = (lane & 3) * 2;
#pragma unroll
    for (int mt = 0; mt < 4; mt++) {
        int r = m0 + warpM * 64 + mt * 16 + crow;
#pragma unroll
        for (int nt = 0; nt < 4; nt++) {
            int c = warpN * 32 + nt * 8 + ccol;
            float b0 = bias[c], b1 = bias[c + 1];
            float v0 = acc[mt][nt][0] + b0;
            float v1 = acc[mt][nt][1] + b1;
            float v2 = acc[mt][nt][2] + b0;
            float v3 = acc[mt][nt][3] + b1;
            if (relu) {
                v0 = fmaxf(v0, 0.f); v1 = fmaxf(v1, 0.f);
                v2 = fmaxf(v2, 0.f); v3 = fmaxf(v3, 0.f);
            }
            if (r < NN)     *(float2*)(out + (size_t)r * W + c)       = make_float2(v0, v1);
            if (r + 8 < NN) *(float2*)(out + (size_t)(r + 8) * W + c) = make_float2(v2, v3);
        }
    }
}

// ---------------- last-layer telescope ----------------
__global__ void wtilde_kernel(const float* __restrict__ W5,
                              const float* __restrict__ lw)
{
    int idx = blockIdx.x * blockDim.x + threadIdx.x;
    if (idx >= 5 * W) return;
    const float* row = W5 + (size_t)idx * W;
    float s = 0.f;
    for (int o = 0; o < W; o++) s += row[o] * lw[o];
    g_WT[idx] = s;
}

__global__ void wt_transform_kernel() {
    int in = threadIdx.x;
    if (in >= W) return;
    float w0 = g_WT[0 * W + in];
    float w1 = g_WT[1 * W + in];
    float w2 = g_WT[2 * W + in];
    float w3 = g_WT[3 * W + in];
    float w4 = g_WT[4 * W + in];
    g_WT[0 * W + in] = w0 - w2 + w4;
    g_WT[1 * W + in] = w1 - 3.f * w3;
    g_WT[2 * W + in] = 2.f * w2 - 8.f * w4;
    g_WT[3 * W + in] = 4.f * w3;
    g_WT[4 * W + in] = 8.f * w4;
}

__global__ void const_kernel(const float* __restrict__ cb,
                             const float* __restrict__ lw,
                             const float* __restrict__ lb)
{
    int lane = threadIdx.x & 31;
    float4 b = ((const float4*)cb)[lane];
    float4 w = ((const float4*)lw)[lane];
    float s = b.x * w.x + b.y * w.y + b.z * w.z + b.w * w.w;
#pragma unroll
    for (int off = 16; off > 0; off >>= 1)
        s += __shfl_xor_sync(0xffffffffu, s, off);
    if (lane == 0) g_c0 = s + lb[0];
}

__global__ void __launch_bounds__(256) u_kernel(
    const float* __restrict__ H, float* __restrict__ U)
{
    __shared__ float wt[5][W];
    for (int i = threadIdx.x; i < 5 * W; i += blockDim.x)
        wt[i / W][i % W] = g_WT[i];
    __syncthreads();

    int warp = (blockIdx.x * blockDim.x + threadIdx.x) >> 5;
    int lane = threadIdx.x & 31;
    if (warp >= NN) return;
    float4 hv = ((const float4*)H)[(size_t)warp * 32 + lane];
    float s[5];
#pragma unroll
    for (int k = 0; k < 5; k++) {
        float4 wv = ((const float4*)wt[k])[lane];
        float p = hv.x * wv.x + hv.y * wv.y + hv.z * wv.z + hv.w * wv.w;
#pragma unroll
        for (int off = 16; off > 0; off >>= 1)
            p += __shfl_xor_sync(0xffffffffu, p, off);
        s[k] = p;
    }
    if (lane == 0) {
        float* o = U + (size_t)warp * 8;
        o[0] = s[0]; o[1] = s[1]; o[2] = s[2]; o[3] = s[3]; o[4] = s[4];
        o[5] = 0.f;  o[6] = 0.f;  o[7] = 0.f;
    }
}

// width-8 propagate: out = L @ U (power basis, no prev)
__global__ void __launch_bounds__(256) prop8_kernel(
    const float* __restrict__ U, float* __restrict__ out)
{
    const int l = threadIdx.x & 7;
    const int g0 = (blockIdx.x * blockDim.x + threadIdx.x) >> 3;
    const int gstride = (PROP_BLOCKS * 256) >> 3;
    for (int node = g0; node < NN; node += gstride) {
        int start = g_rowptr[node];
        int end   = g_rowptr[node + 1];
        float acc = 0.f;
        for (int i = start; i < end; i++) {
            int s = g_csr_src[i];
            float w = g_csr_w[i];
            acc += w * U[s * 8 + l];
        }
        out[node * 8 + l] = acc;
    }
}

__global__ void combine_kernel(
    const float* __restrict__ Y0, const float* __restrict__ Y1,
    const float* __restrict__ Y2, const float* __restrict__ Y3,
    const float* __restrict__ Y4, float* __restrict__ out)
{
    int j = blockIdx.x * blockDim.x + threadIdx.x;
    if (j >= NN) return;
    float s = Y0[(size_t)j * 8 + 0] + Y1[(size_t)j * 8 + 1] + Y2[(size_t)j * 8 + 2]
            + Y3[(size_t)j * 8 + 3] + Y4[(size_t)j * 8 + 4] + g_c0;
    out[j] = s;
}

// ---------------- launcher ----------------
extern "C" void kernel_launch(void* const* d_in, const int* in_sizes, int n_in,
                              void* d_out, int out_size)
{
    const float* x      = (const float*)d_in[0];
    const void*  ei     = d_in[1];
    const float* conv_w = (const float*)d_in[2];
    const float* conv_b = (const float*)d_in[3];
    const float* lin_w  = (const float*)d_in[4];
    const float* lin_b  = (const float*)d_in[5];
    float* out = (float*)d_out;

    float *pP1, *pP2, *pP3, *pP4, *pHA, *pHB, *pWM, *pU, *pY1, *pY2, *pY3, *pY4;
    cudaGetSymbolAddress((void**)&pP1, g_P1);
    cudaGetSymbolAddress((void**)&pP2, g_P2);
    cudaGetSymbolAddress((void**)&pP3, g_P3);
    cudaGetSymbolAddress((void**)&pP4, g_P4);
    cudaGetSymbolAddress((void**)&pHA, g_HA);
    cudaGetSymbolAddress((void**)&pHB, g_HB);
    cudaGetSymbolAddress((void**)&pWM, g_WMOD);
    cudaGetSymbolAddress((void**)&pU, g_U);
    cudaGetSymbolAddress((void**)&pY1, g_Y1);
    cudaGetSymbolAddress((void**)&pY2, g_Y2);
    cudaGetSymbolAddress((void**)&pY3, g_Y3);
    cudaGetSymbolAddress((void**)&pY4, g_Y4);

    detect_kernel<<<1, 256>>>((const int*)ei);
    init_kernel<<<NBLK, 256>>>();
    deg_kernel<<<(NE + 255) / 256, 256>>>(ei);
    dsum_kernel<<<NBLK, 256>>>();
    bscan_kernel<<<1, 256>>>();
    rowptr_kernel<<<NBLK, 256>>>();
    fill_kernel<<<(NE + 255) / 256, 256>>>(ei);
    wmod_kernel<<<(5 * W * W + 255) / 256, 256>>>(conv_w);
    wtilde_kernel<<<3, 256>>>(conv_w + (size_t)5 * 5 * W * W, lin_w);
    wt_transform_kernel<<<1, 128>>>();
    const_kernel<<<1, 32>>>(conv_b + 5 * W, lin_w, lin_b);

    const int GG = (NN + 127) / 128;

    // first 5 conv layers (all with relu); power basis: Pk = L @ P(k-1)
    const float* Hin = x;
    float* Hout = pHA;
    for (int l = 0; l < 5; l++) {
        propagate_kernel<<<PROP_BLOCKS, 256>>>(Hin, pP1);
        propagate_kernel<<<PROP_BLOCKS, 256>>>(pP1, pP2);
        propagate_kernel<<<PROP_BLOCKS, 256>>>(pP2, pP3);
        propagate_kernel<<<PROP_BLOCKS, 256>>>(pP3, pP4);
        Ptr5 T;
        T.p[0] = Hin; T.p[1] = pP1; T.p[2] = pP2; T.p[3] = pP3; T.p[4] = pP4;
        gemm5_mma_kernel<<<GG, 256>>>(T, pWM + (size_t)l * 5 * W * W,
                                      conv_b + l * W, Hout, 1);
        Hin = Hout;
        Hout = (Hout == pHA) ? pHB : pHA;
    }

    // telescoped last layer (power basis)
    u_kernel<<<(NN + 7) / 8, 256>>>(Hin, pU);
    prop8_kernel<<<PROP_BLOCKS, 256>>>(pU, pY1);
    prop8_kernel<<<PROP_BLOCKS, 256>>>(pY1, pY2);
    prop8_kernel<<<PROP_BLOCKS, 256>>>(pY2, pY3);
    prop8_kernel<<<PROP_BLOCKS, 256>>>(pY3, pY4);
    combine_kernel<<<(NN + 255) / 256, 256>>>(pU, pY1, pY2, pY3, pY4, out);
}